// round 1
// baseline (speedup 1.0000x reference)
#include <cuda_runtime.h>
#include <cstdint>

// KV Q4 dequant:
//   packed: int32 words, value in [0,256). low nibble -> element 2j, high nibble -> element 2j+1
//   out[e] = nibble * scale[block] + bias[block], block = e / 32  (16 packed words per block)
// Output layout: [ k_dequant (8,388,608 f32) | v_dequant (8,388,608 f32) ]
// (reference reshapes are views only; flat order is preserved)

__global__ __launch_bounds__(256)
void kv_dequant_kernel(const int4* __restrict__ k_packed,
                       const float* __restrict__ k_scale,
                       const float* __restrict__ k_bias,
                       const int4* __restrict__ v_packed,
                       const float* __restrict__ v_scale,
                       const float* __restrict__ v_bias,
                       float4* __restrict__ out,
                       int n_vec_per_tensor,   // packed words / 4
                       int out_vec_offset_v)   // float4 offset of v region in out
{
    int tid = blockIdx.x * blockDim.x + threadIdx.x;
    int total = 2 * n_vec_per_tensor;
    if (tid >= total) return;

    bool is_v = tid >= n_vec_per_tensor;
    int i = is_v ? tid - n_vec_per_tensor : tid;

    const int4*  src = is_v ? v_packed : k_packed;
    const float* sc  = is_v ? v_scale  : k_scale;
    const float* bi  = is_v ? v_bias   : k_bias;

    int4 w = __ldg(&src[i]);

    // block index: each block = 16 packed words = 4 int4 vectors
    int blk = i >> 2;
    float s = __ldg(&sc[blk]);
    float b = __ldg(&bi[blk]);

    float4 o0, o1;
    o0.x = (float)(w.x & 15) * s + b;
    o0.y = (float)(w.x >> 4) * s + b;
    o0.z = (float)(w.y & 15) * s + b;
    o0.w = (float)(w.y >> 4) * s + b;
    o1.x = (float)(w.z & 15) * s + b;
    o1.y = (float)(w.z >> 4) * s + b;
    o1.z = (float)(w.w & 15) * s + b;
    o1.w = (float)(w.w >> 4) * s + b;

    float4* dst = out + (is_v ? out_vec_offset_v : 0);
    dst[2 * i]     = o0;
    dst[2 * i + 1] = o1;
}

extern "C" void kernel_launch(void* const* d_in, const int* in_sizes, int n_in,
                              void* d_out, int out_size)
{
    // metadata order: k_packed, k_scale, k_bias, v_packed, v_scale, v_bias, batch_size
    const int4*  k_packed = (const int4*) d_in[0];
    const float* k_scale  = (const float*)d_in[1];
    const float* k_bias   = (const float*)d_in[2];
    const int4*  v_packed = (const int4*) d_in[3];
    const float* v_scale  = (const float*)d_in[4];
    const float* v_bias   = (const float*)d_in[5];

    int n_packed_words   = in_sizes[0];          // 4,194,304
    int n_vec            = n_packed_words / 4;   // 1,048,576 int4 per tensor
    int out_floats_per_t = n_packed_words * 2;   // 8,388,608
    int out_vec_offset_v = out_floats_per_t / 4; // float4 offset of V region

    int total_threads = 2 * n_vec;
    int block = 256;
    int grid  = (total_threads + block - 1) / block;

    kv_dequant_kernel<<<grid, block>>>(k_packed, k_scale, k_bias,
                                       v_packed, v_scale, v_bias,
                                       (float4*)d_out,
                                       n_vec, out_vec_offset_v);
}